// round 1
// baseline (speedup 1.0000x reference)
#include <cuda_runtime.h>
#include <math.h>

// ---------------------------------------------------------------------------
// DBASolver: Schur-complement pose/depth update.
//   B=16, N=131072, C=2, P=6 (sizes derived at launch from in_sizes).
// Pass 1: per-node H_pd/g_d/inv_H_dd -> scratch; block-reduce 27 per-batch
//         scalars (21 sym H_eff + 6 g_eff) into per-block partials.
// Pass 2: one block: finish reduction, assemble/dampen H, 6x6 solve (double),
//         NaN check, write clipped delta_pose, stash raw pose for pass 3.
// Pass 3: delta_depth = inv_H_dd * (g_d - H_pd . pose), clip, write.
// ---------------------------------------------------------------------------

#define MAXB 16
#define MAXN 131072
#define ITER 8
#define TPB  256
#define MAXCHUNKS 256   // >= ceil(MAXN / (TPB*ITER)) = 64

// per-node scratch: {hpd0..3} {hpd4,hpd5,g_d,inv}
__device__ float4 g_scratch[(size_t)MAXB * MAXN * 2];
// per-block partial reductions: [b][chunk][27]
__device__ float  g_partial[(size_t)MAXB * MAXCHUNKS * 27];
// raw (unclipped) pose for pass 3, and global nan flag
__device__ float  g_pose[MAXB * 6];
__device__ int    g_nanflag;

__global__ void __launch_bounds__(TPB)
pass1_kernel(const float* __restrict__ r, const float* __restrict__ w,
             const float* __restrict__ Jp, const float* __restrict__ Jd,
             const float* __restrict__ lmbda, int N)
{
    const int b = blockIdx.y;
    const size_t bn0 = (size_t)b * N;
    const size_t base = (size_t)blockIdx.x * (TPB * ITER);

    float lm = lmbda[b];
    float safe_l = isnan(lm) ? 100.0f : lm;
    safe_l = fmaxf(safe_l, 0.001f);

    const float4* __restrict__ Jp4 = (const float4*)Jp;
    const float2* __restrict__ r2  = (const float2*)r;
    const float2* __restrict__ w2  = (const float2*)w;
    const float2* __restrict__ jd2 = (const float2*)Jd;

    float acc[27];
#pragma unroll
    for (int i = 0; i < 27; i++) acc[i] = 0.0f;

#pragma unroll
    for (int it = 0; it < ITER; it++) {
        size_t n = base + (size_t)it * TPB + threadIdx.x;
        if (n < (size_t)N) {
            size_t idx = bn0 + n;
            float4 jpA = Jp4[idx * 3 + 0];
            float4 jpB = Jp4[idx * 3 + 1];
            float4 jpC = Jp4[idx * 3 + 2];
            float2 rv  = r2[idx];
            float2 wv  = w2[idx];
            float2 jdv = jd2[idx];

            float conf = wv.x, nl = wv.y;
            float jp0[6] = { jpA.x, jpA.y, jpA.z, jpA.w, jpB.x, jpB.y };
            float jp1[6] = { jpB.z, jpB.w, jpC.x, jpC.y, jpC.z, jpC.w };

            float hpd[6], gp[6];
#pragma unroll
            for (int p = 0; p < 6; p++) {
                hpd[p] = conf * (jp0[p] * jdv.x + jp1[p] * jdv.y);
                gp[p]  = conf * (jp0[p] * rv.x  + jp1[p] * rv.y);
            }
            float hdd = conf * (jdv.x * jdv.x + jdv.y * jdv.y);
            float gd  = conf * (jdv.x * rv.x  + jdv.y * rv.y);
            float inv = 1.0f / fmaxf(hdd + safe_l + nl + 1e-4f, 1e-4f);

            int k = 0;
#pragma unroll
            for (int p = 0; p < 6; p++) {
#pragma unroll
                for (int q = p; q < 6; q++) {
                    acc[k++] += conf * (jp0[p] * jp0[q] + jp1[p] * jp1[q])
                                - hpd[p] * inv * hpd[q];
                }
            }
#pragma unroll
            for (int p = 0; p < 6; p++)
                acc[21 + p] += gp[p] - hpd[p] * inv * gd;

            g_scratch[idx * 2 + 0] = make_float4(hpd[0], hpd[1], hpd[2], hpd[3]);
            g_scratch[idx * 2 + 1] = make_float4(hpd[4], hpd[5], gd, inv);
        }
    }

    // warp reduce 27 values
#pragma unroll
    for (int i = 0; i < 27; i++) {
#pragma unroll
        for (int off = 16; off > 0; off >>= 1)
            acc[i] += __shfl_down_sync(0xFFFFFFFFu, acc[i], off);
    }

    __shared__ float sred[TPB / 32][27];
    int warp = threadIdx.x >> 5, lane = threadIdx.x & 31;
    if (lane == 0) {
#pragma unroll
        for (int i = 0; i < 27; i++) sred[warp][i] = acc[i];
    }
    __syncthreads();

    if (threadIdx.x < 27) {
        float s = 0.0f;
#pragma unroll
        for (int wd = 0; wd < TPB / 32; wd++) s += sred[wd][threadIdx.x];
        g_partial[((size_t)b * gridDim.x + blockIdx.x) * 27 + threadIdx.x] = s;
    }
}

__global__ void __launch_bounds__(512)
solve_kernel(const float* __restrict__ lmbda, const int* __restrict__ iter_idx,
             float* __restrict__ out, int B, int nchunks)
{
    __shared__ float sH[MAXB][27];
    __shared__ int   s_nan;
    int t = threadIdx.x;
    if (t == 0) s_nan = 0;

    if (t < B * 27) {
        int b = t / 27, i = t % 27;
        float s = 0.0f;
        for (int c = 0; c < nchunks; c++)
            s += g_partial[((size_t)b * nchunks + c) * 27 + i];
        sH[b][i] = s;
    }
    __syncthreads();

    float pose[6];
    int b = t;
    if (b < B) {
        float lm = lmbda[b];
        float safe_l = isnan(lm) ? 100.0f : lm;
        safe_l = fmaxf(safe_l, 0.001f);

        float H[6][6], g[6];
        int k = 0;
        for (int p = 0; p < 6; p++)
            for (int q = p; q < 6; q++) { float v = sH[b][k++]; H[p][q] = v; H[q][p] = v; }
        for (int p = 0; p < 6; p++) g[p] = sH[b][21 + p];

        for (int i = 0; i < 6; i++) H[i][i] += safe_l;

        int iters = iter_idx[0];
        if (iters >= 2) {
            for (int p = 3; p < 6; p++) g[p] = 0.0f;
            for (int p = 3; p < 6; p++)
                for (int q = 3; q < 6; q++) H[p][q] += 1.0e8f;
        }
        for (int i = 0; i < 6; i++) H[i][i] += 1.0f;
        for (int i = 0; i < 6; i++) H[i][i] += 0.01f * H[i][i];

        // 6x6 solve in double, partial pivoting
        double A[6][7];
        for (int i = 0; i < 6; i++) {
            for (int j = 0; j < 6; j++) A[i][j] = (double)H[i][j];
            A[i][6] = (double)g[i];
        }
        for (int c = 0; c < 6; c++) {
            int piv = c; double mx = fabs(A[c][c]);
            for (int rr = c + 1; rr < 6; rr++) {
                double a = fabs(A[rr][c]);
                if (a > mx) { mx = a; piv = rr; }
            }
            if (piv != c) {
                for (int j = c; j < 7; j++) {
                    double tmp = A[c][j]; A[c][j] = A[piv][j]; A[piv][j] = tmp;
                }
            }
            double d = A[c][c];
            for (int rr = c + 1; rr < 6; rr++) {
                double f = A[rr][c] / d;
                for (int j = c; j < 7; j++) A[rr][j] -= f * A[c][j];
            }
        }
        double x[6];
        for (int i = 5; i >= 0; i--) {
            double s = A[i][6];
            for (int j = i + 1; j < 6; j++) s -= A[i][j] * x[j];
            x[i] = s / A[i][i];
        }

        bool anynan = false;
        for (int p = 0; p < 6; p++) {
            pose[p] = (float)x[p];
            g_pose[b * 6 + p] = pose[p];      // raw pose feeds pass 3
            if (isnan(pose[p])) anynan = true;
        }
        if (anynan) atomicOr(&s_nan, 1);
    }
    __syncthreads();

    if (t == 0) g_nanflag = s_nan;
    if (b < B) {
        for (int p = 0; p < 6; p++) {
            float v = fminf(fmaxf(pose[p], -2.0f), 2.0f);
            out[b * 6 + p] = s_nan ? 0.0f : v;
        }
    }
}

__global__ void __launch_bounds__(TPB)
depth_kernel(float* __restrict__ out, int N, int B)
{
    size_t idx = (size_t)blockIdx.x * TPB + threadIdx.x;
    size_t total = (size_t)B * N;
    if (idx >= total) return;
    int b = (int)(idx / (size_t)N);

    float4 s0 = g_scratch[idx * 2 + 0];
    float4 s1 = g_scratch[idx * 2 + 1];
    const float* pose = &g_pose[b * 6];

    float v = s0.x * pose[0] + s0.y * pose[1] + s0.z * pose[2]
            + s0.w * pose[3] + s1.x * pose[4] + s1.y * pose[5];
    float dd = s1.w * (s1.z - v);
    dd = fminf(fmaxf(dd, -5.0f), 5.0f);
    if (g_nanflag) dd = 0.0f;
    out[(size_t)B * 6 + idx] = dd;
}

extern "C" void kernel_launch(void* const* d_in, const int* in_sizes, int n_in,
                              void* d_out, int out_size)
{
    const float* r      = (const float*)d_in[0];
    const float* w      = (const float*)d_in[1];
    const float* Jp     = (const float*)d_in[2];
    const float* Jd     = (const float*)d_in[3];
    const float* lmbda  = (const float*)d_in[4];
    const int*   iter_i = (const int*)d_in[5];
    float* out = (float*)d_out;

    int B = in_sizes[4];                 // lmbda has B elements
    int N = in_sizes[0] / (2 * B);       // r is (B, N, 2)

    int tile   = TPB * ITER;
    int chunks = (N + tile - 1) / tile;

    dim3 g1(chunks, B);
    pass1_kernel<<<g1, TPB>>>(r, w, Jp, Jd, lmbda, N);
    solve_kernel<<<1, 512>>>(lmbda, iter_i, out, B, chunks);

    size_t total = (size_t)B * N;
    int blocks = (int)((total + TPB - 1) / TPB);
    depth_kernel<<<blocks, TPB>>>(out, N, B);
}